// round 16
// baseline (speedup 1.0000x reference)
#include <cuda_runtime.h>
#include <cstdint>

// DimeNetPP radius-graph distances + triplet angles.
// TMA-staged, double-buffered: CTA = 2 warps; each warp processes 4 rows
// through 2 alternating private smem tiles. Per row: zero tile (STS.128),
// adjacency + dists, scatter ~55 symmetric angles (STS.32), then one
// cp.async.bulk (9216 B) smem->GMEM. Tile reuse gated only by
// wait_group.read (TMA smem-read done), never by GMEM-write completion.
// Inputs: [0] atomic_ns (unused), [1] coords f32 [N,3], [2] batch_node_vec (unused)
// Output: f32, dists [B,48,48] then angles [B,48,48,48].

#define MOL_B 128
#define MM 48
#define THREADS 64               // 2 warps per CTA
#define ROWS_PER_WARP 4
#define CTAS (MOL_B * MM / (2 * ROWS_PER_WARP))   // 768
#define CUTOFF_F 1.5f
#define TILE_F (MM * MM)         // 2304 floats = 9216 bytes

// Branch-free atan2 for y >= 0, (x,y) != (0,0). Max rel err ~1.3e-4.
__device__ __forceinline__ float fast_atan2_pos(float y, float x)
{
    const float ax = fabsf(x);
    const float mn = fminf(y, ax);
    const float mx = fmaxf(y, ax);
    const float t  = __fdividef(mn, mx);
    const float s  = t * t;
    float p = fmaf(s, 0.0208351f, -0.0851330f);
    p = fmaf(s, p, 0.1801410f);
    p = fmaf(s, p, -0.3302995f);
    p = fmaf(s, p, 0.9998660f);
    p = p * t;
    p = (y > ax) ? (1.57079632679f - p) : p;
    p = (x < 0.0f) ? (3.14159265359f - p) : p;
    return p;
}

__device__ __forceinline__ uint32_t smem_u32(const void* p)
{
    uint32_t a;
    asm("{ .reg .u64 t; cvta.to.shared.u64 t, %1; cvt.u32.u64 %0, t; }"
        : "=r"(a) : "l"(p));
    return a;
}

__global__ __launch_bounds__(THREADS)
void dimenet_kernel(const float* __restrict__ coords, float* __restrict__ out)
{
    const int tid  = threadIdx.x;
    const int wid  = tid >> 5;
    const int lane = tid & 31;
    const int warpg = blockIdx.x * 2 + wid;          // 0 .. 1535
    const int row0  = warpg * ROWS_PER_WARP;         // first of 4 rows

    __shared__ float tiles[2][2][TILE_F];            // [warp][buf] 36.9 KB
    __shared__ float nx[2][MM], ny[2][MM], nz[2][MM], nd2[2][MM];
    __shared__ int   nk[2][MM];

    float* __restrict__ dists  = out;
    float* __restrict__ angles = out + (size_t)MOL_B * MM * MM;
    const unsigned below = (1u << lane) - 1u;

    #pragma unroll
    for (int r = 0; r < ROWS_PER_WARP; r++) {
        const int row = row0 + r;
        const int b   = row / MM;
        const int j   = row - b * MM;
        const int buf = r & 1;
        float* const tile = tiles[wid][buf];
        const float* __restrict__ mc = coords + b * (MM * 3);

        // Gate tile reuse on the TMA having READ it (not on GMEM landing).
        if (r >= 2 && lane == 0)
            asm volatile("cp.async.bulk.wait_group.read 1;" ::: "memory");
        __syncwarp();

        // Zero the tile (576 float4, 18 per lane).
        {
            float4* t4 = reinterpret_cast<float4*>(tile);
            const float4 z = make_float4(0.f, 0.f, 0.f, 0.f);
            #pragma unroll
            for (int t = 0; t < 18; t++)
                t4[lane + t * 32] = z;
        }

        // Adjacency + dists row + compacted neighbor vectors.
        const float px = __ldg(&mc[j * 3 + 0]);
        const float py = __ldg(&mc[j * 3 + 1]);
        const float pz = __ldg(&mc[j * 3 + 2]);
        float* const drow = dists + (size_t)row * MM;

        const int q0 = lane;
        const float vx0 = __ldg(&mc[q0 * 3 + 0]) - px;
        const float vy0 = __ldg(&mc[q0 * 3 + 1]) - py;
        const float vz0 = __ldg(&mc[q0 * 3 + 2]) - pz;
        const float d20 = vx0 * vx0 + vy0 * vy0 + vz0 * vz0;
        const float dist0 = sqrtf(d20);
        const bool adj0 = (q0 != j) && (dist0 < CUTOFF_F);
        drow[q0] = adj0 ? dist0 : 0.0f;
        const unsigned m0 = __ballot_sync(0xffffffffu, adj0);

        bool adj1 = false;
        const int q1 = lane + 32;
        float vx1 = 0.f, vy1 = 0.f, vz1 = 0.f, d21 = 0.f;
        if (lane < 16) {
            vx1 = __ldg(&mc[q1 * 3 + 0]) - px;
            vy1 = __ldg(&mc[q1 * 3 + 1]) - py;
            vz1 = __ldg(&mc[q1 * 3 + 2]) - pz;
            d21 = vx1 * vx1 + vy1 * vy1 + vz1 * vz1;
            const float dist1 = sqrtf(d21);
            adj1 = (q1 != j) && (dist1 < CUTOFF_F);
            drow[q1] = adj1 ? dist1 : 0.0f;
        }
        const unsigned m1 = __ballot_sync(0xffffffffu, adj1);

        const int c0 = __popc(m0);
        const int c  = c0 + __popc(m1);
        if (adj0) {
            const int s = __popc(m0 & below);
            nx[wid][s] = vx0; ny[wid][s] = vy0; nz[wid][s] = vz0;
            nd2[wid][s] = d20; nk[wid][s] = q0;
        }
        if (adj1) {
            const int s = c0 + __popc(m1 & below);
            nx[wid][s] = vx1; ny[wid][s] = vy1; nz[wid][s] = vz1;
            nd2[wid][s] = d21; nk[wid][s] = q1;
        }
        __syncwarp();   // zeros + neighbor arrays visible warp-wide

        // Strict upper-triangle symmetric pairs -> scatter mirrors into tile.
        const int T = (c * (c - 1)) >> 1;
        for (int g = lane; g < T; g += 32) {
            int pi = (int)((1.0f + sqrtf(fmaf(8.f, (float)g, 1.f))) * 0.5f);
            if ((pi * (pi - 1)) >> 1 > g) pi--;
            if ((pi * (pi + 1)) >> 1 <= g) pi++;
            const int ki = g - ((pi * (pi - 1)) >> 1);

            const float vix = nx[wid][pi], viy = ny[wid][pi], viz = nz[wid][pi];
            const float vkx = nx[wid][ki], vky = ny[wid][ki], vkz = nz[wid][ki];
            const float a  = vix * vkx + viy * vky + viz * vkz;
            const float b2 = fmaxf(nd2[wid][pi] * nd2[wid][ki] - a * a, 0.f);
            const float ang = fast_atan2_pos(sqrtf(b2), a);

            const int ii = nk[wid][pi];
            const int kk = nk[wid][ki];
            tile[ii * MM + kk] = ang;
            tile[kk * MM + ii] = ang;
        }
        __syncwarp();   // tile complete

        // Bulk store this row's tile; no completion wait here.
        if (lane == 0) {
            float* const gdst = angles + (size_t)row * TILE_F;
            const uint32_t ssrc = smem_u32(tile);
            asm volatile("fence.proxy.async.shared::cta;" ::: "memory");
            asm volatile(
                "cp.async.bulk.global.shared::cta.bulk_group [%0], [%1], %2;"
                :: "l"(gdst), "r"(ssrc), "r"((uint32_t)(TILE_F * 4)) : "memory");
            asm volatile("cp.async.bulk.commit_group;" ::: "memory");
        }
    }

    // Final drain (end of kernel: cost is invisible).
    if (lane == 0)
        asm volatile("cp.async.bulk.wait_group 0;" ::: "memory");
}

extern "C" void kernel_launch(void* const* d_in, const int* in_sizes, int n_in,
                              void* d_out, int out_size)
{
    const float* coords = (const float*)d_in[1];
    float* out = (float*)d_out;
    dimenet_kernel<<<CTAS, THREADS>>>(coords, out);
}

// round 17
// speedup vs baseline: 1.2702x; 1.2702x over previous
#include <cuda_runtime.h>
#include <cstdint>

// DimeNetPP radius-graph distances + triplet angles.
// R14 structure (best: 14.4us): one warp per row, private smem tile, one
// cp.async.bulk (9216 B) per row. CHANGE: the final drain waits only for the
// TMA to finish READING smem (wait_group.read 0) -- safe for CTA exit -- not
// for GMEM write completion, which the kernel boundary guarantees anyway.
// This un-parks warps from the backed-up TMA write queue and lets warp slots
// recycle at compute speed.
// Inputs: [0] atomic_ns (unused), [1] coords f32 [N,3], [2] batch_node_vec (unused)
// Output: f32, dists [B,48,48] then angles [B,48,48,48].

#define MOL_B 128
#define MM 48
#define THREADS 128
#define CTAS (MOL_B * MM / 4)    // 1536 CTAs x 4 warps = 6144 rows
#define CUTOFF_F 1.5f
#define TILE_F (MM * MM)         // 2304 floats = 9216 bytes

// Branch-free atan2 for y >= 0, (x,y) != (0,0). Max rel err ~1.3e-4.
__device__ __forceinline__ float fast_atan2_pos(float y, float x)
{
    const float ax = fabsf(x);
    const float mn = fminf(y, ax);
    const float mx = fmaxf(y, ax);
    const float t  = __fdividef(mn, mx);
    const float s  = t * t;
    float p = fmaf(s, 0.0208351f, -0.0851330f);
    p = fmaf(s, p, 0.1801410f);
    p = fmaf(s, p, -0.3302995f);
    p = fmaf(s, p, 0.9998660f);
    p = p * t;
    p = (y > ax) ? (1.57079632679f - p) : p;
    p = (x < 0.0f) ? (3.14159265359f - p) : p;
    return p;
}

__device__ __forceinline__ uint32_t smem_u32(const void* p)
{
    uint32_t a;
    asm("{ .reg .u64 t; cvta.to.shared.u64 t, %1; cvt.u32.u64 %0, t; }"
        : "=r"(a) : "l"(p));
    return a;
}

__global__ __launch_bounds__(THREADS)
void dimenet_kernel(const float* __restrict__ coords, float* __restrict__ out)
{
    const int tid  = threadIdx.x;
    const int wid  = tid >> 5;
    const int lane = tid & 31;
    const int row  = blockIdx.x * 4 + wid;           // 0 .. 6143
    const int b    = row / MM;                       // molecule
    const int j    = row - b * MM;                   // center row

    __shared__ float tile[4][TILE_F];                // 4 x 9216 B, per-warp
    __shared__ float nx[4][MM], ny[4][MM], nz[4][MM], nd2[4][MM];
    __shared__ int   nk[4][MM];

    const float* __restrict__ mc = coords + b * (MM * 3);
    float* __restrict__ dists  = out;
    float* __restrict__ angles = out + (size_t)MOL_B * MM * MM;

    // Zero this warp's private smem tile (576 float4, 18 per lane).
    {
        float4* t4 = reinterpret_cast<float4*>(tile[wid]);
        const float4 z = make_float4(0.f, 0.f, 0.f, 0.f);
        #pragma unroll
        for (int t = 0; t < 18; t++)
            t4[lane + t * 32] = z;
    }

    // Adjacency + dists row + compacted neighbor vectors (warp-local).
    const float px = __ldg(&mc[j * 3 + 0]);
    const float py = __ldg(&mc[j * 3 + 1]);
    const float pz = __ldg(&mc[j * 3 + 2]);
    const unsigned below = (1u << lane) - 1u;
    float* const drow = dists + ((size_t)b * MM + j) * MM;

    const int q0 = lane;
    const float vx0 = __ldg(&mc[q0 * 3 + 0]) - px;
    const float vy0 = __ldg(&mc[q0 * 3 + 1]) - py;
    const float vz0 = __ldg(&mc[q0 * 3 + 2]) - pz;
    const float d20 = vx0 * vx0 + vy0 * vy0 + vz0 * vz0;
    const float dist0 = sqrtf(d20);
    const bool adj0 = (q0 != j) && (dist0 < CUTOFF_F);
    drow[q0] = adj0 ? dist0 : 0.0f;
    const unsigned m0 = __ballot_sync(0xffffffffu, adj0);

    bool adj1 = false;
    const int q1 = lane + 32;
    float vx1 = 0.f, vy1 = 0.f, vz1 = 0.f, d21 = 0.f;
    if (lane < 16) {
        vx1 = __ldg(&mc[q1 * 3 + 0]) - px;
        vy1 = __ldg(&mc[q1 * 3 + 1]) - py;
        vz1 = __ldg(&mc[q1 * 3 + 2]) - pz;
        d21 = vx1 * vx1 + vy1 * vy1 + vz1 * vz1;
        const float dist1 = sqrtf(d21);
        adj1 = (q1 != j) && (dist1 < CUTOFF_F);
        drow[q1] = adj1 ? dist1 : 0.0f;
    }
    const unsigned m1 = __ballot_sync(0xffffffffu, adj1);

    const int c0 = __popc(m0);
    const int c  = c0 + __popc(m1);
    if (adj0) {
        const int s = __popc(m0 & below);
        nx[wid][s] = vx0; ny[wid][s] = vy0; nz[wid][s] = vz0;
        nd2[wid][s] = d20; nk[wid][s] = q0;
    }
    if (adj1) {
        const int s = c0 + __popc(m1 & below);
        nx[wid][s] = vx1; ny[wid][s] = vy1; nz[wid][s] = vz1;
        nd2[wid][s] = d21; nk[wid][s] = q1;
    }
    __syncwarp();   // neighbor arrays + tile zeros visible warp-wide

    // Strict upper-triangle symmetric pairs -> scatter both mirrors into smem.
    const int T = (c * (c - 1)) >> 1;
    for (int g = lane; g < T; g += 32) {
        int pi = (int)((1.0f + sqrtf(fmaf(8.f, (float)g, 1.f))) * 0.5f);
        if ((pi * (pi - 1)) >> 1 > g) pi--;
        if ((pi * (pi + 1)) >> 1 <= g) pi++;
        const int ki = g - ((pi * (pi - 1)) >> 1);

        const float vix = nx[wid][pi], viy = ny[wid][pi], viz = nz[wid][pi];
        const float vkx = nx[wid][ki], vky = ny[wid][ki], vkz = nz[wid][ki];
        const float a  = vix * vkx + viy * vky + viz * vkz;
        const float b2 = fmaxf(nd2[wid][pi] * nd2[wid][ki] - a * a, 0.f);
        const float ang = fast_atan2_pos(sqrtf(b2), a);

        const int ii = nk[wid][pi];
        const int kk = nk[wid][ki];
        tile[wid][ii * MM + kk] = ang;
        tile[wid][kk * MM + ii] = ang;
    }
    __syncwarp();   // tile complete

    // One bulk async store: smem tile -> this row's 9216-byte GMEM slab.
    // Wait only for the TMA to finish READING smem (CTA-exit safety);
    // GMEM write completion is covered by the kernel boundary.
    if (lane == 0) {
        float* const gdst = angles + (size_t)row * TILE_F;
        const uint32_t ssrc = smem_u32(&tile[wid][0]);
        asm volatile("fence.proxy.async.shared::cta;" ::: "memory");
        asm volatile(
            "cp.async.bulk.global.shared::cta.bulk_group [%0], [%1], %2;"
            :: "l"(gdst), "r"(ssrc), "r"((uint32_t)(TILE_F * 4)) : "memory");
        asm volatile("cp.async.bulk.commit_group;" ::: "memory");
        asm volatile("cp.async.bulk.wait_group.read 0;" ::: "memory");
    }
}

extern "C" void kernel_launch(void* const* d_in, const int* in_sizes, int n_in,
                              void* d_out, int out_size)
{
    const float* coords = (const float*)d_in[1];
    float* out = (float*)d_out;
    dimenet_kernel<<<CTAS, THREADS>>>(coords, out);
}